// round 7
// baseline (speedup 1.0000x reference)
#include <cuda_runtime.h>
#include <math.h>

#define SPH 132            // H1s row stride (floats)
#define H2P 130            // H2s row stride (floats)

// ---------------- device scratch -------------------------------------------
__device__ float  g_U[(size_t)50000 * 128];  // exact 64-term prefix chains
__device__ float  g_z[800000];               // fp32 z, serial-chain bitwise target
__device__ double g_part[8192];              // per-CTA sum of z^2 (fp64)
__device__ float  g_norm32;                  // fl32(max(sqrt(sum), 1e-12))

// ---------------- f32x2 helpers (two independent fp32 FMAs, bitwise = fmaf) -
static __device__ __forceinline__ unsigned long long ffma2(
    unsigned long long a, unsigned long long b, unsigned long long c) {
    unsigned long long d;
    asm("fma.rn.f32x2 %0, %1, %2, %3;" : "=l"(d) : "l"(a), "l"(b), "l"(c));
    return d;
}
static __device__ __forceinline__ unsigned long long dup2(float a) {
    unsigned long long d; unsigned int ai = __float_as_uint(a);
    asm("mov.b64 %0, {%1, %1};" : "=l"(d) : "r"(ai));
    return d;
}
static __device__ __forceinline__ void unpack2(unsigned long long v, float& lo, float& hi) {
    unsigned int l, h;
    asm("mov.b64 {%0, %1}, %2;" : "=r"(l), "=r"(h) : "l"(v));
    lo = __uint_as_float(l); hi = __uint_as_float(h);
}

// ---------------- stage 1: U[n][m] = serial FMA chain over k=0..63 ----------
__global__ __launch_bounds__(256)
void node_u_kernel(const float* __restrict__ feats,
                   const float* __restrict__ W1, int N)
{
    __shared__ float fs[64 * 64];
    const int tid = threadIdx.x;
    const int h = tid & 127;
    const int half = tid >> 7;
    const int n0 = blockIdx.x * 64;
    int cnt = N - n0; if (cnt > 64) cnt = 64;
    if (cnt <= 0) return;

    float w[64];
    const float4* wp = (const float4*)(W1 + h * 128);
#pragma unroll
    for (int i = 0; i < 16; i++) {
        float4 q = __ldg(wp + i);
        w[4*i] = q.x; w[4*i+1] = q.y; w[4*i+2] = q.z; w[4*i+3] = q.w;
    }
    const float4* fsrc = (const float4*)(feats + (size_t)n0 * 64);
    for (int i = tid; i < cnt * 16; i += 256)
        ((float4*)fs)[i] = __ldg(fsrc + i);
    __syncthreads();

    const int nb = half * 32;
    const int ne = (cnt < nb + 32) ? cnt : (nb + 32);
    for (int nn = nb; nn < ne; nn++) {
        const float* fp = fs + nn * 64;
        float acc = 0.f;
#pragma unroll
        for (int k = 0; k < 64; k++) acc = fmaf(w[k], fp[k], acc);  // serial ascending
        g_U[(size_t)(n0 + nn) * 128 + h] = acc;
    }
}

// ---------------- stage 2: per-128-edge tile, layers 1-3 -------------------
__global__ __launch_bounds__(256, 1)
void edge_kernel(const int* __restrict__ rows, const int* __restrict__ cols,
                 const float* __restrict__ feats,
                 const float* __restrict__ W1g, const float* __restrict__ b1g,
                 const float* __restrict__ W2g, const float* __restrict__ b2g,
                 const float* __restrict__ W3g, const float* __restrict__ b3g,
                 int E)
{
    extern __shared__ float smem[];
    float* R1   = smem;                 // 17664 floats, reused
    float* H1s  = smem + 17664;         // [128 m][SPH]  (phase A out / B in)
    float* W1bs = R1;                   // [128 m][64 k]
    float* Fcs  = R1 + 8192;            // [64 k][SPH]
    float* Us   = R1 + 8192 + 8448;     // [8 row][128 m]
    float* W2s  = R1;                   // phase B: [128 m][128 k]
    float* H2s  = H1s;                  // phase C alias: [128 e][H2P]

    __shared__ float  W3s[128];
    __shared__ double dred[4];

    const int tid = threadIdx.x;
    const int e0 = blockIdx.x * 128;

    // ---- stage loads for phase A ----
    {
        const float4* w1v = (const float4*)W1g;
#pragma unroll
        for (int it = 0; it < 8; it++) {
            int idx = tid + it * 256;
            int m = idx >> 4, kq = idx & 15;
            ((float4*)W1bs)[idx] = __ldg(w1v + m * 32 + 16 + kq);  // W1[m][64+4kq..]
        }
    }
    {
        const int w = tid >> 5, lane = tid & 31;
        const int kq = lane & 15;
#pragma unroll
        for (int ii = 0; ii < 8; ii++) {
            int eloc = w * 16 + ii * 2 + (lane >> 4);
            int g = e0 + eloc;
            float4 q = make_float4(0.f, 0.f, 0.f, 0.f);
            if (g < E) {
                int c = __ldg(cols + g);
                q = __ldg((const float4*)(feats + (size_t)c * 64) + kq);
            }
            Fcs[(kq*4+0)*SPH + eloc] = q.x;
            Fcs[(kq*4+1)*SPH + eloc] = q.y;
            Fcs[(kq*4+2)*SPH + eloc] = q.z;
            Fcs[(kq*4+3)*SPH + eloc] = q.w;
        }
    }
#pragma unroll
    for (int t = 0; t < 4; t++) {
        int i = tid + t * 256;
        int r = i >> 7, m = i & 127;
        int ge = e0 + r * 16;
        int grow = (ge < E) ? __ldg(rows + ge) : 0;
        Us[i] = g_U[(size_t)grow * 128 + m];
    }
    if (tid < 128) W3s[tid] = __ldg(W3g + tid);
    __syncthreads();

    const int tx = tid & 15, ty = tid >> 4;
    unsigned long long acc[8][4];

    // ---- phase A: continue layer-1 chain over col half (k=64..127) ----
    {
        const int rA = tx >> 2, rB = 4 + (tx >> 2);
#pragma unroll
        for (int i = 0; i < 8; i++) {
            int m = (i < 4) ? (ty*4 + i) : (64 + ty*4 + (i-4));
            unsigned long long uA = dup2(Us[rA*128 + m]);
            unsigned long long uB = dup2(Us[rB*128 + m]);
            acc[i][0] = uA; acc[i][1] = uA;
            acc[i][2] = uB; acc[i][3] = uB;
        }
        const float* a0p = W1bs + (ty*4) * 64;
        const float* a1p = W1bs + (64 + ty*4) * 64;
#pragma unroll 2
        for (int k4 = 0; k4 < 16; k4++) {
            float a[8][4];
#pragma unroll
            for (int i = 0; i < 4; i++) {
                float4 q  = *(const float4*)(a0p + i*64 + k4*4);
                a[i][0]=q.x; a[i][1]=q.y; a[i][2]=q.z; a[i][3]=q.w;
                float4 q2 = *(const float4*)(a1p + i*64 + k4*4);
                a[4+i][0]=q2.x; a[4+i][1]=q2.y; a[4+i][2]=q2.z; a[4+i][3]=q2.w;
            }
#pragma unroll
            for (int kk = 0; kk < 4; kk++) {
                const float* bk = Fcs + (k4*4 + kk) * SPH;
                ulonglong2 q0 = *(const ulonglong2*)(bk + tx*4);
                ulonglong2 q1 = *(const ulonglong2*)(bk + 64 + tx*4);
#pragma unroll
                for (int i = 0; i < 8; i++) {
                    unsigned long long ad = dup2(a[i][kk]);
                    acc[i][0] = ffma2(ad, q0.x, acc[i][0]);
                    acc[i][1] = ffma2(ad, q0.y, acc[i][1]);
                    acc[i][2] = ffma2(ad, q1.x, acc[i][2]);
                    acc[i][3] = ffma2(ad, q1.y, acc[i][3]);
                }
            }
        }
#pragma unroll
        for (int i = 0; i < 8; i++) {
            int m = (i < 4) ? (ty*4 + i) : (64 + ty*4 + (i-4));
            float bb = __ldg(b1g + m);
#pragma unroll
            for (int p = 0; p < 4; p++) {
                float lo, hi; unpack2(acc[i][p], lo, hi);
                int e = (p < 2) ? (tx*4 + p*2) : (64 + tx*4 + (p-2)*2);
                H1s[m*SPH + e]     = fmaxf(lo + bb, 0.f);
                H1s[m*SPH + e + 1] = fmaxf(hi + bb, 0.f);
            }
        }
    }
    __syncthreads();

    // ---- stage W2 (overwrites R1) ----
    {
        const float4* src = (const float4*)W2g;
        float4* dst = (float4*)W2s;
#pragma unroll 4
        for (int it = 0; it < 16; it++)
            dst[tid + it*256] = __ldg(src + tid + it*256);
    }
    __syncthreads();

    // ---- phase B: layer-2 serial ascending-k chain ----
#pragma unroll
    for (int i = 0; i < 8; i++)
#pragma unroll
        for (int p = 0; p < 4; p++) acc[i][p] = 0ULL;
    {
        const float* a0p = W2s + (ty*4) * 128;
        const float* a1p = W2s + (64 + ty*4) * 128;
#pragma unroll 2
        for (int k4 = 0; k4 < 32; k4++) {
            float a[8][4];
#pragma unroll
            for (int i = 0; i < 4; i++) {
                float4 q  = *(const float4*)(a0p + i*128 + k4*4);
                a[i][0]=q.x; a[i][1]=q.y; a[i][2]=q.z; a[i][3]=q.w;
                float4 q2 = *(const float4*)(a1p + i*128 + k4*4);
                a[4+i][0]=q2.x; a[4+i][1]=q2.y; a[4+i][2]=q2.z; a[4+i][3]=q2.w;
            }
#pragma unroll
            for (int kk = 0; kk < 4; kk++) {
                const float* bk = H1s + (k4*4 + kk) * SPH;
                ulonglong2 q0 = *(const ulonglong2*)(bk + tx*4);
                ulonglong2 q1 = *(const ulonglong2*)(bk + 64 + tx*4);
#pragma unroll
                for (int i = 0; i < 8; i++) {
                    unsigned long long ad = dup2(a[i][kk]);
                    acc[i][0] = ffma2(ad, q0.x, acc[i][0]);
                    acc[i][1] = ffma2(ad, q0.y, acc[i][1]);
                    acc[i][2] = ffma2(ad, q1.x, acc[i][2]);
                    acc[i][3] = ffma2(ad, q1.y, acc[i][3]);
                }
            }
        }
    }
    __syncthreads();   // all H1s reads done before aliasing it as H2s
#pragma unroll
    for (int i = 0; i < 8; i++) {
        int m = (i < 4) ? (ty*4 + i) : (64 + ty*4 + (i-4));
        float bb = __ldg(b2g + m);
#pragma unroll
        for (int p = 0; p < 4; p++) {
            float lo, hi; unpack2(acc[i][p], lo, hi);
            int e = (p < 2) ? (tx*4 + p*2) : (64 + tx*4 + (p-2)*2);
            H2s[e*H2P + m]     = fmaxf(lo + bb, 0.f);
            H2s[(e+1)*H2P + m] = fmaxf(hi + bb, 0.f);
        }
    }
    __syncthreads();

    // ---- phase C: z = serial ascending fp32 chain over m, + b3 -----------
    if (tid < 128) {
        const float* hrow = H2s + tid * H2P;
        float z = 0.f;
#pragma unroll
        for (int m = 0; m < 128; m++)
            z = fmaf(W3s[m], hrow[m], z);          // serial, ascending (GEMM order)
        z = z + __ldg(b3g);                        // b3 = 0: exact

        double sq = 0.0;
        int g = e0 + tid;
        if (g < E) { g_z[g] = z; sq = (double)z * (double)z; }
#pragma unroll
        for (int m2 = 16; m2; m2 >>= 1)
            sq += __shfl_xor_sync(0xffffffffu, sq, m2);
        if ((tid & 31) == 0) dred[tid >> 5] = sq;
    }
    __syncthreads();
    if (tid == 0)
        g_part[blockIdx.x] = (dred[0] + dred[1]) + (dred[2] + dred[3]);
}

// ---------------- stage 3: exact (fp64) ||z||, rounded to fp32 --------------
__global__ void reduce_partials_kernel(int nb)
{
    __shared__ double sm[256];
    double s = 0.0;
    for (int i = threadIdx.x; i < nb; i += 256) s += g_part[i];
    sm[threadIdx.x] = s;
    __syncthreads();
    for (int st = 128; st > 0; st >>= 1) {
        if (threadIdx.x < st) sm[threadIdx.x] += sm[threadIdx.x + st];
        __syncthreads();
    }
    if (threadIdx.x == 0)
        g_norm32 = (float)fmax(sqrt(sm[0]), 1e-12);
}

// ---------------- stage 4: fp32-faithful softmax + top-8 with fp32 ties -----
__global__ __launch_bounds__(256)
void finalize_kernel(float* __restrict__ out, int N)
{
    const int t = blockIdx.x * 256 + threadIdx.x;
    const int warp = t >> 5;
    const int lane = threadIdx.x & 31;
    const int row = warp * 2 + (lane >> 4);
    const int j = lane & 15;
    const bool valid = row < N;
    const int e = row * 16 + j;

    const float nrm = g_norm32;
    float zn = valid ? __fdiv_rn(g_z[e], nrm) : -1e30f;   // fp32 division, as ref

    float mx = zn;
#pragma unroll
    for (int m = 8; m; m >>= 1)
        mx = fmaxf(mx, __shfl_xor_sync(0xffffffffu, mx, m, 16));

    const float a = zn - mx;                              // fp32 subtract, as ref
    float ez = (float)exp((double)a);                     // ~correctly-rounded expf
    if (!valid) ez = 0.f;

    // segment_sum emulation: fp32 adds in ascending index order
    float s = 0.f;
#pragma unroll
    for (int i = 0; i < 16; i++)
        s += __shfl_sync(0xffffffffu, ez, i, 16);

    const float pi = __fdiv_rn(ez, s);                    // fp32 division, as ref

    // keep iff at most 7 strictly-greater pi in the row (ties at 8th kept)
    int r = 0;
#pragma unroll
    for (int i = 0; i < 16; i++) {
        float v = __shfl_sync(0xffffffffu, pi, i, 16);
        r += (v > pi) ? 1 : 0;
    }
    if (valid) out[e] = (r <= 7) ? pi : 0.f;
}

// ---------------- launch ----------------------------------------------------
extern "C" void kernel_launch(void* const* d_in, const int* in_sizes, int n_in,
                              void* d_out, int out_size)
{
    const float* feats = (const float*)d_in[0];
    const int*   idx   = (const int*)  d_in[1];
    const float* W1    = (const float*)d_in[2];
    const float* b1    = (const float*)d_in[3];
    const float* W2    = (const float*)d_in[4];
    const float* b2    = (const float*)d_in[5];
    const float* W3    = (const float*)d_in[6];
    const float* b3    = (const float*)d_in[7];
    float* out = (float*)d_out;

    const int N = in_sizes[0] / 64;
    const int E = in_sizes[1] / 2;
    const int* rows = idx;
    const int* cols = idx + E;

    node_u_kernel<<<(N + 63) / 64, 256>>>(feats, W1, N);

    const int EB = (E + 127) / 128;
    const size_t smemB = (size_t)(17664 + 16896) * sizeof(float);  // 138240 B
    cudaFuncSetAttribute(edge_kernel,
                         cudaFuncAttributeMaxDynamicSharedMemorySize, (int)smemB);
    edge_kernel<<<EB, 256, smemB>>>(rows, cols, feats, W1, b1, W2, b2, W3, b3, E);

    reduce_partials_kernel<<<1, 256>>>(EB);

    finalize_kernel<<<(N + 15) / 16, 256>>>(out, N);
}

// round 8
// speedup vs baseline: 1.0558x; 1.0558x over previous
#include <cuda_runtime.h>
#include <math.h>

#define SPH 132            // Fcs/H1s row stride (floats)
#define H2P 130            // H2s row stride (floats)

// dynamic smem layout (floats)
#define OFF_W1B 0          // [128 m][64 k]          8192
#define OFF_W2  8192       // [128 m][128 k]        16384
#define OFF_FCS 24576      // [64 k][SPH]            8448
#define OFF_H1  33024      // [128 m][SPH] (alias H2) 16896
#define OFF_US  49920      // [8 row][128 m]         1024
#define SMEM_FLOATS 50944  // 203776 bytes

// ---------------- device scratch -------------------------------------------
__device__ float  g_U[(size_t)50000 * 128];  // exact 64-term prefix chains
__device__ float  g_z[800000];               // fp32 z (bitwise target)
__device__ double g_part[1024];              // per-CTA sum of z^2 (fp64)
__device__ float  g_norm32;                  // fl32(max(sqrt(sum), 1e-12))

// ---------------- f32x2 helpers (two independent fp32 FMAs, bitwise = fmaf) -
static __device__ __forceinline__ unsigned long long ffma2(
    unsigned long long a, unsigned long long b, unsigned long long c) {
    unsigned long long d;
    asm("fma.rn.f32x2 %0, %1, %2, %3;" : "=l"(d) : "l"(a), "l"(b), "l"(c));
    return d;
}
static __device__ __forceinline__ unsigned long long dup2(float a) {
    unsigned long long d; unsigned int ai = __float_as_uint(a);
    asm("mov.b64 %0, {%1, %1};" : "=l"(d) : "r"(ai));
    return d;
}
static __device__ __forceinline__ void unpack2(unsigned long long v, float& lo, float& hi) {
    unsigned int l, h;
    asm("mov.b64 {%0, %1}, %2;" : "=r"(l), "=r"(h) : "l"(v));
    lo = __uint_as_float(l); hi = __uint_as_float(h);
}

// ---------------- stage 1: U[n][m] = serial FMA chain over k=0..63 ----------
__global__ __launch_bounds__(256)
void node_u_kernel(const float* __restrict__ feats,
                   const float* __restrict__ W1, int N)
{
    __shared__ float fs[64 * 64];
    const int tid = threadIdx.x;
    const int h = tid & 127;
    const int half = tid >> 7;
    const int n0 = blockIdx.x * 64;
    int cnt = N - n0; if (cnt > 64) cnt = 64;
    if (cnt <= 0) return;

    float w[64];
    const float4* wp = (const float4*)(W1 + h * 128);
#pragma unroll
    for (int i = 0; i < 16; i++) {
        float4 q = __ldg(wp + i);
        w[4*i] = q.x; w[4*i+1] = q.y; w[4*i+2] = q.z; w[4*i+3] = q.w;
    }
    const float4* fsrc = (const float4*)(feats + (size_t)n0 * 64);
    for (int i = tid; i < cnt * 16; i += 256)
        ((float4*)fs)[i] = __ldg(fsrc + i);
    __syncthreads();

    const int nb = half * 32;
    const int ne = (cnt < nb + 32) ? cnt : (nb + 32);
    for (int nn = nb; nn < ne; nn++) {
        const float* fp = fs + nn * 64;
        float acc = 0.f;
#pragma unroll
        for (int k = 0; k < 64; k++) acc = fmaf(w[k], fp[k], acc);  // serial ascending
        g_U[(size_t)(n0 + nn) * 128 + h] = acc;
    }
}

// ---------------- gather helpers (into Fcs / Us for a tile) ------------------
static __device__ __forceinline__ void gather_tile_256(
    float* Fcs, float* Us, const int* rows, const int* cols,
    const float* feats, int e0, int E, int tid)
{
#pragma unroll
    for (int it = 0; it < 8; it++) {
        int idx = tid + it * 256;           // 0..2047
        int e = idx >> 4, kq = idx & 15;
        int g = e0 + e;
        float4 q = make_float4(0.f, 0.f, 0.f, 0.f);
        if (g < E) {
            int c = __ldg(cols + g);
            q = __ldg((const float4*)(feats + (size_t)c * 64) + kq);
        }
        Fcs[(kq*4+0)*SPH + e] = q.x;
        Fcs[(kq*4+1)*SPH + e] = q.y;
        Fcs[(kq*4+2)*SPH + e] = q.z;
        Fcs[(kq*4+3)*SPH + e] = q.w;
    }
#pragma unroll
    for (int t = 0; t < 4; t++) {
        int i = tid + t * 256;
        int r = i >> 7, m = i & 127;
        int ge = e0 + r * 16;
        int grow = (ge < E) ? __ldg(rows + ge) : 0;
        Us[i] = g_U[(size_t)grow * 128 + m];
    }
}

static __device__ __forceinline__ void gather_tile_128(
    float* Fcs, float* Us, const int* rows, const int* cols,
    const float* feats, int e0, int E, int tid2)
{
#pragma unroll
    for (int b = 0; b < 4; b++) {
        float4 q[4]; int eL[4], kqL[4];
#pragma unroll
        for (int u = 0; u < 4; u++) {
            int idx = tid2 + (b*4 + u) * 128;   // 0..2047
            int e = idx >> 4, kq = idx & 15;
            int g = e0 + e;
            float4 qq = make_float4(0.f, 0.f, 0.f, 0.f);
            if (g < E) {
                int c = __ldg(cols + g);
                qq = __ldg((const float4*)(feats + (size_t)c * 64) + kq);
            }
            q[u] = qq; eL[u] = e; kqL[u] = kq;
        }
#pragma unroll
        for (int u = 0; u < 4; u++) {
            Fcs[(kqL[u]*4+0)*SPH + eL[u]] = q[u].x;
            Fcs[(kqL[u]*4+1)*SPH + eL[u]] = q[u].y;
            Fcs[(kqL[u]*4+2)*SPH + eL[u]] = q[u].z;
            Fcs[(kqL[u]*4+3)*SPH + eL[u]] = q[u].w;
        }
    }
#pragma unroll
    for (int t = 0; t < 8; t++) {
        int ge = e0 + t * 16;
        int grow = (ge < E) ? __ldg(rows + ge) : 0;
        Us[t * 128 + tid2] = g_U[(size_t)grow * 128 + tid2];
    }
}

// ---------------- stage 2: persistent edge kernel, layers 1-3 ---------------
__global__ __launch_bounds__(256, 1)
void edge_kernel(const int* __restrict__ rows, const int* __restrict__ cols,
                 const float* __restrict__ feats,
                 const float* __restrict__ W1g, const float* __restrict__ b1g,
                 const float* __restrict__ W2g, const float* __restrict__ b2g,
                 const float* __restrict__ W3g, const float* __restrict__ b3g,
                 int E, int EB)
{
    extern __shared__ float smem[];
    float* W1bs = smem + OFF_W1B;
    float* W2s  = smem + OFF_W2;
    float* Fcs  = smem + OFF_FCS;
    float* H1s  = smem + OFF_H1;
    float* H2s  = H1s;                  // phase C alias: [128 e][H2P]
    float* Us   = smem + OFF_US;

    __shared__ float  W3s[128];
    __shared__ double dred[4];

    const int tid = threadIdx.x;

    // ---- resident weights (loaded once) ----
    {
        const float4* w1v = (const float4*)W1g;
#pragma unroll
        for (int it = 0; it < 8; it++) {
            int idx = tid + it * 256;
            int m = idx >> 4, kq = idx & 15;
            ((float4*)W1bs)[idx] = __ldg(w1v + m * 32 + 16 + kq);  // W1[m][64+4kq..]
        }
        const float4* src = (const float4*)W2g;
        float4* dst = (float4*)W2s;
#pragma unroll 4
        for (int it = 0; it < 16; it++)
            dst[tid + it*256] = __ldg(src + tid + it*256);
        if (tid < 128) W3s[tid] = __ldg(W3g + tid);
    }

    const int tx = tid & 15, ty = tid >> 4;
    double sq_acc = 0.0;

    int tile = blockIdx.x;
    if (tile < EB)
        gather_tile_256(Fcs, Us, rows, cols, feats, tile * 128, E, tid);
    __syncthreads();

    for (; tile < EB; tile += gridDim.x) {
        const int e0 = tile * 128;
        unsigned long long acc[8][4];

        // ---- phase A: continue layer-1 chain over col half (k=64..127) ----
        {
            const int rA = tx >> 2, rB = 4 + (tx >> 2);
#pragma unroll
            for (int i = 0; i < 8; i++) {
                int m = (i < 4) ? (ty*4 + i) : (64 + ty*4 + (i-4));
                unsigned long long uA = dup2(Us[rA*128 + m]);
                unsigned long long uB = dup2(Us[rB*128 + m]);
                acc[i][0] = uA; acc[i][1] = uA;
                acc[i][2] = uB; acc[i][3] = uB;
            }
            const float* a0p = W1bs + (ty*4) * 64;
            const float* a1p = W1bs + (64 + ty*4) * 64;
#pragma unroll 2
            for (int k4 = 0; k4 < 16; k4++) {
                float a[8][4];
#pragma unroll
                for (int i = 0; i < 4; i++) {
                    float4 q  = *(const float4*)(a0p + i*64 + k4*4);
                    a[i][0]=q.x; a[i][1]=q.y; a[i][2]=q.z; a[i][3]=q.w;
                    float4 q2 = *(const float4*)(a1p + i*64 + k4*4);
                    a[4+i][0]=q2.x; a[4+i][1]=q2.y; a[4+i][2]=q2.z; a[4+i][3]=q2.w;
                }
#pragma unroll
                for (int kk = 0; kk < 4; kk++) {
                    const float* bk = Fcs + (k4*4 + kk) * SPH;
                    ulonglong2 q0 = *(const ulonglong2*)(bk + tx*4);
                    ulonglong2 q1 = *(const ulonglong2*)(bk + 64 + tx*4);
#pragma unroll
                    for (int i = 0; i < 8; i++) {
                        unsigned long long ad = dup2(a[i][kk]);
                        acc[i][0] = ffma2(ad, q0.x, acc[i][0]);
                        acc[i][1] = ffma2(ad, q0.y, acc[i][1]);
                        acc[i][2] = ffma2(ad, q1.x, acc[i][2]);
                        acc[i][3] = ffma2(ad, q1.y, acc[i][3]);
                    }
                }
            }
#pragma unroll
            for (int i = 0; i < 8; i++) {
                int m = (i < 4) ? (ty*4 + i) : (64 + ty*4 + (i-4));
                float bb = __ldg(b1g + m);
#pragma unroll
                for (int p = 0; p < 4; p++) {
                    float lo, hi; unpack2(acc[i][p], lo, hi);
                    int e = (p < 2) ? (tx*4 + p*2) : (64 + tx*4 + (p-2)*2);
                    H1s[m*SPH + e]     = fmaxf(lo + bb, 0.f);
                    H1s[m*SPH + e + 1] = fmaxf(hi + bb, 0.f);
                }
            }
        }
        __syncthreads();

        // ---- phase B: layer-2 serial ascending-k chain ----
#pragma unroll
        for (int i = 0; i < 8; i++)
#pragma unroll
            for (int p = 0; p < 4; p++) acc[i][p] = 0ULL;
        {
            const float* a0p = W2s + (ty*4) * 128;
            const float* a1p = W2s + (64 + ty*4) * 128;
#pragma unroll 2
            for (int k4 = 0; k4 < 32; k4++) {
                float a[8][4];
#pragma unroll
                for (int i = 0; i < 4; i++) {
                    float4 q  = *(const float4*)(a0p + i*128 + k4*4);
                    a[i][0]=q.x; a[i][1]=q.y; a[i][2]=q.z; a[i][3]=q.w;
                    float4 q2 = *(const float4*)(a1p + i*128 + k4*4);
                    a[4+i][0]=q2.x; a[4+i][1]=q2.y; a[4+i][2]=q2.z; a[4+i][3]=q2.w;
                }
#pragma unroll
                for (int kk = 0; kk < 4; kk++) {
                    const float* bk = H1s + (k4*4 + kk) * SPH;
                    ulonglong2 q0 = *(const ulonglong2*)(bk + tx*4);
                    ulonglong2 q1 = *(const ulonglong2*)(bk + 64 + tx*4);
#pragma unroll
                    for (int i = 0; i < 8; i++) {
                        unsigned long long ad = dup2(a[i][kk]);
                        acc[i][0] = ffma2(ad, q0.x, acc[i][0]);
                        acc[i][1] = ffma2(ad, q0.y, acc[i][1]);
                        acc[i][2] = ffma2(ad, q1.x, acc[i][2]);
                        acc[i][3] = ffma2(ad, q1.y, acc[i][3]);
                    }
                }
            }
        }
        __syncthreads();   // all H1s reads done before aliasing it as H2s
#pragma unroll
        for (int i = 0; i < 8; i++) {
            int m = (i < 4) ? (ty*4 + i) : (64 + ty*4 + (i-4));
            float bb = __ldg(b2g + m);
#pragma unroll
            for (int p = 0; p < 4; p++) {
                float lo, hi; unpack2(acc[i][p], lo, hi);
                int e = (p < 2) ? (tx*4 + p*2) : (64 + tx*4 + (p-2)*2);
                H2s[e*H2P + m]     = fmaxf(lo + bb, 0.f);
                H2s[(e+1)*H2P + m] = fmaxf(hi + bb, 0.f);
            }
        }
        __syncthreads();

        // ---- phase C (tid<128): z chain; tid>=128: prefetch next tile ----
        if (tid < 128) {
            const float* hrow = H2s + tid * H2P;
            float z = 0.f;
#pragma unroll
            for (int m = 0; m < 128; m++)
                z = fmaf(W3s[m], hrow[m], z);      // serial, ascending (GEMM order)
            z = z + __ldg(b3g);                    // b3 = 0: exact

            int g = e0 + tid;
            if (g < E) {
                g_z[g] = z;
                sq_acc += (double)z * (double)z;
            }
        } else {
            int nt = tile + gridDim.x;
            if (nt < EB)
                gather_tile_128(Fcs, Us, rows, cols, feats, nt * 128, E, tid - 128);
        }
        __syncthreads();
    }

    // ---- per-CTA deterministic sum of z^2 ----
    if (tid < 128) {
        double s = sq_acc;
#pragma unroll
        for (int m2 = 16; m2; m2 >>= 1)
            s += __shfl_xor_sync(0xffffffffu, s, m2);
        if ((tid & 31) == 0) dred[tid >> 5] = s;
    }
    __syncthreads();
    if (tid == 0)
        g_part[blockIdx.x] = (dred[0] + dred[1]) + (dred[2] + dred[3]);
}

// ---------------- stage 3: exact (fp64) ||z||, rounded to fp32 --------------
__global__ void reduce_partials_kernel(int nb)
{
    __shared__ double sm[256];
    double s = 0.0;
    for (int i = threadIdx.x; i < nb; i += 256) s += g_part[i];
    sm[threadIdx.x] = s;
    __syncthreads();
    for (int st = 128; st > 0; st >>= 1) {
        if (threadIdx.x < st) sm[threadIdx.x] += sm[threadIdx.x + st];
        __syncthreads();
    }
    if (threadIdx.x == 0)
        g_norm32 = (float)fmax(sqrt(sm[0]), 1e-12);
}

// ---------------- stage 4: fp32-faithful softmax + top-8 with fp32 ties -----
__global__ __launch_bounds__(256)
void finalize_kernel(float* __restrict__ out, int N)
{
    const int t = blockIdx.x * 256 + threadIdx.x;
    const int warp = t >> 5;
    const int lane = threadIdx.x & 31;
    const int row = warp * 2 + (lane >> 4);
    const int j = lane & 15;
    const bool valid = row < N;
    const int e = row * 16 + j;

    const float nrm = g_norm32;
    float zn = valid ? __fdiv_rn(g_z[e], nrm) : -1e30f;   // fp32 division, as ref

    float mx = zn;
#pragma unroll
    for (int m = 8; m; m >>= 1)
        mx = fmaxf(mx, __shfl_xor_sync(0xffffffffu, mx, m, 16));

    const float a = zn - mx;                              // fp32 subtract, as ref
    float ez = (float)exp((double)a);                     // ~correctly-rounded expf
    if (!valid) ez = 0.f;

    // segment_sum emulation: fp32 adds in ascending index order
    float s = 0.f;
#pragma unroll
    for (int i = 0; i < 16; i++)
        s += __shfl_sync(0xffffffffu, ez, i, 16);

    const float pi = __fdiv_rn(ez, s);                    // fp32 division, as ref

    // keep iff at most 7 strictly-greater pi in the row (ties at 8th kept)
    int r = 0;
#pragma unroll
    for (int i = 0; i < 16; i++) {
        float v = __shfl_sync(0xffffffffu, pi, i, 16);
        r += (v > pi) ? 1 : 0;
    }
    if (valid) out[e] = (r <= 7) ? pi : 0.f;
}

// ---------------- launch ----------------------------------------------------
extern "C" void kernel_launch(void* const* d_in, const int* in_sizes, int n_in,
                              void* d_out, int out_size)
{
    const float* feats = (const float*)d_in[0];
    const int*   idx   = (const int*)  d_in[1];
    const float* W1    = (const float*)d_in[2];
    const float* b1    = (const float*)d_in[3];
    const float* W2    = (const float*)d_in[4];
    const float* b2    = (const float*)d_in[5];
    const float* W3    = (const float*)d_in[6];
    const float* b3    = (const float*)d_in[7];
    float* out = (float*)d_out;

    const int N = in_sizes[0] / 64;
    const int E = in_sizes[1] / 2;
    const int* rows = idx;
    const int* cols = idx + E;

    static int nsm = 0;
    if (nsm == 0) {
        cudaDeviceGetAttribute(&nsm, cudaDevAttrMultiProcessorCount, 0);
        if (nsm <= 0 || nsm > 1024) nsm = 148;
        cudaFuncSetAttribute(edge_kernel,
                             cudaFuncAttributeMaxDynamicSharedMemorySize,
                             SMEM_FLOATS * (int)sizeof(float));
    }

    node_u_kernel<<<(N + 63) / 64, 256>>>(feats, W1, N);

    const int EB = (E + 127) / 128;
    edge_kernel<<<nsm, 256, SMEM_FLOATS * sizeof(float)>>>(
        rows, cols, feats, W1, b1, W2, b2, W3, b3, E, EB);

    reduce_partials_kernel<<<1, 256>>>(nsm);

    finalize_kernel<<<(N + 15) / 16, 256>>>(out, N);
}